// round 6
// baseline (speedup 1.0000x reference)
#include <cuda_runtime.h>
#include <cstdint>

#define CIN   128
#define CHID  256
#define COUT  128
#define HW    1600
#define TP    128
#define NT    512
#define NTILE 13

#define SX 136     // x / W1 / h row stride (mod 32 == 8 -> conflict-free)
#define SW 72      // W2 row stride

// SMEM float offsets
#define OXS 0                      // x  [128 c][136]
#define OW1 17408                  // W1 [64 ch][136]
#define OHS 26112                  // h  [64 ch][136]
#define OW2 34816                  // W2 [128 oc][72]
#define OGB 44032                  // gated b2 [128]
#define SMB ((44032 + 128) * 4)    // 176640 B

__device__ float sW1[8 * 4 * 64 * SX];    // tf32-rounded, fragment-permuted
__device__ float sW2[8 * 4 * 128 * SW];
__device__ int   g_idx[256];

__device__ __forceinline__ uint32_t smem_u32(const void* p) {
    uint32_t a;
    asm("{ .reg .u64 t; cvta.to.shared.u64 t, %1; cvt.u32.u64 %0, t; }" : "=r"(a) : "l"(p));
    return a;
}
__device__ __forceinline__ float tf32f(float v) {
    uint32_t r;
    asm("cvt.rna.tf32.f32 %0, %1;" : "=r"(r) : "f"(v));
    return __uint_as_float(r);
}
__device__ __forceinline__ void mma8(float (&d)[4], const float (&a)[4], float b0, float b1) {
    asm("mma.sync.aligned.m16n8k8.row.col.f32.tf32.tf32.f32 "
        "{%0,%1,%2,%3}, {%4,%5,%6,%7}, {%8,%9}, {%0,%1,%2,%3};"
        : "+f"(d[0]), "+f"(d[1]), "+f"(d[2]), "+f"(d[3])
        : "r"(__float_as_uint(a[0])), "r"(__float_as_uint(a[1])),
          "r"(__float_as_uint(a[2])), "r"(__float_as_uint(a[3])),
          "r"(__float_as_uint(b0)),  "r"(__float_as_uint(b1)));
}
#define CPA16(dst, src)      asm volatile("cp.async.ca.shared.global [%0], [%1], 16;" :: "r"(dst), "l"(src))
#define CPA16Z(dst, src, sz) asm volatile("cp.async.ca.shared.global [%0], [%1], 16, %2;" :: "r"(dst), "l"(src), "r"(sz))
#define CPA_COMMIT()         asm volatile("cp.async.commit_group;" ::: "memory")
#define CPA_WAIT0()          asm volatile("cp.async.wait_group 0;" ::: "memory")

// fragment column permutation: within 8-col chunk, col w -> 2*(w&3) + ((w&4)>>2)
__device__ __forceinline__ int permc(int c) {
    return 8 * (c >> 3) + 2 * (c & 3) + ((c & 4) >> 2);
}

__global__ void prep_idx(const int* __restrict__ raw) {
    __shared__ int odd_nz;
    if (threadIdx.x == 0) odd_nz = 0;
    __syncthreads();
    if (threadIdx.x < 128) {
        if (raw[2 * threadIdx.x + 1] != 0) atomicAdd(&odd_nz, 1);
    }
    __syncthreads();
    bool is64 = (odd_nz == 0);
    g_idx[threadIdx.x] = is64 ? raw[2 * threadIdx.x] : raw[threadIdx.x];
}

// permute + tf32-round weights into scratch (once per launch, ~2us)
__global__ void prep_w(const float* __restrict__ W1, const float* __restrict__ W2) {
    int idx = blockIdx.x * blockDim.x + threadIdx.x;     // 0..262143
    {   // W1[e][256 ch][128 c] -> sW1[(e*4+j)*64+row][perm(c)]
        int e = idx >> 15, r = (idx >> 7) & 255, c = idx & 127;
        int j = r >> 6, row = r & 63;
        sW1[(size_t)((e * 4 + j) * 64 + row) * SX + permc(c)] = tf32f(W1[idx]);
    }
    {   // W2[e][128 oc][256 ch] -> sW2[(e*4+j)*128+row][perm(c)]
        int e = idx >> 15, row = (idx >> 8) & 127, cc = idx & 255;
        int j = cc >> 6, c = cc & 63;
        sW2[(size_t)((e * 4 + j) * 128 + row) * SW + permc(c)] = tf32f(W2[idx]);
    }
}

__global__ __launch_bounds__(NT, 1)
void moe_tf32(const float* __restrict__ x,
              const float* __restrict__ gate_w,
              const float* __restrict__ b1,
              const float* __restrict__ b2,
              float* __restrict__ out)
{
    extern __shared__ float sm[];
    const uint32_t smb = smem_u32(sm);
    const int tid  = threadIdx.x;
    const int lane = tid & 31;
    const int warp = tid >> 5;
    const int g    = lane >> 2;
    const int t    = lane & 3;
    const int wm1  = warp >> 3, wn1 = warp & 7;   // GEMM1: 2 ch-groups x 8 px-groups
    const int wm2  = warp >> 2, wn2 = warp & 3;   // GEMM2: 4 oc-groups x 4 px-groups
    const int b    = blockIdx.y;
    const int p0   = blockIdx.x * TP;

    const int   e0 = g_idx[b * 2],           e1 = g_idx[b * 2 + 1];
    const float g0 = __ldg(&gate_w[b * 2]);
    const float g1 = __ldg(&gate_w[b * 2 + 1]);

    if (tid < 128)
        sm[OGB + tid] = g0 * __ldg(&b2[e0 * COUT + tid]) + g1 * __ldg(&b2[e1 * COUT + tid]);

    // ---- x tile: pure cp.async, natural [c][px] layout (zfill OOB) ----
    {
        const float* xb = x + (size_t)b * CIN * HW + p0;
        #pragma unroll
        for (int i = 0; i < 8; i++) {
            int f = tid + i * NT, row = f >> 5, seg = f & 31;
            int ok = (p0 + seg * 4 < HW);
            const float* src = ok ? (xb + (size_t)row * HW + seg * 4) : x;
            CPA16Z(smb + (uint32_t)(OXS + row * SX + seg * 4) * 4, src, ok ? 16 : 0);
        }
    }
    // ---- W1 chunk 0 from scratch ----
    {
        const float* w1s = sW1 + (size_t)(e0 * 4) * 64 * SX;
        #pragma unroll
        for (int i = 0; i < 4; i++) {
            int f = tid + i * NT, row = f >> 5, seg = f & 31;
            CPA16(smb + (uint32_t)(OW1 + row * SX + seg * 4) * 4, w1s + row * SX + seg * 4);
        }
    }
    CPA_COMMIT();
    CPA_WAIT0();
    // ---- in-place tf32 rounding of x (thread-local chunks) ----
    #pragma unroll
    for (int i = 0; i < 8; i++) {
        int f = tid + i * NT, row = f >> 5, seg = f & 31;
        float4* p = (float4*)(sm + OXS + row * SX + seg * 4);
        float4 v = *p;
        *p = make_float4(tf32f(v.x), tf32f(v.y), tf32f(v.z), tf32f(v.w));
    }

    float acc2[2][4][4];
    #pragma unroll
    for (int m = 0; m < 2; m++)
        #pragma unroll
        for (int n = 0; n < 4; n++)
            #pragma unroll
            for (int q = 0; q < 4; q++) acc2[m][n][q] = 0.f;

    __syncthreads();

    #pragma unroll 1
    for (int it = 0; it < 8; it++) {
        const int   e    = (it < 4) ? e0 : e1;
        const int   j    = it & 3;
        const float gate = (it < 4) ? g0 : g1;

        // ---- W2(it) cp.async (lands during GEMM1) ----
        {
            const float* w2s = sW2 + (size_t)(e * 4 + j) * 128 * SW;
            #pragma unroll
            for (int i = 0; i < 4; i++) {
                int f = tid + i * NT, row = f >> 4, seg = f & 15;
                CPA16(smb + (uint32_t)(OW2 + row * SW + seg * 4) * 4, w2s + row * SW + seg * 4);
            }
            CPA_COMMIT();
        }

        // ---- bias (per A-fragment row) ----
        float bia[2][2];
        {
            const float* b1p = b1 + e * CHID + j * 64 + wm1 * 32;
            #pragma unroll
            for (int mi = 0; mi < 2; mi++) {
                bia[mi][0] = __ldg(b1p + 16 * mi + g);
                bia[mi][1] = __ldg(b1p + 16 * mi + 8 + g);
            }
        }

        // ---- GEMM1: D1[ch 32][px 16] per warp; A=W1 frag(LDS.64x2), B=x scalar ----
        float acc1[2][2][4];
        #pragma unroll
        for (int m = 0; m < 2; m++)
            #pragma unroll
            for (int n = 0; n < 2; n++)
                #pragma unroll
                for (int q = 0; q < 4; q++) acc1[m][n][q] = 0.f;

        #pragma unroll 4
        for (int k = 0; k < 16; k++) {
            float a[2][4];
            #pragma unroll
            for (int mi = 0; mi < 2; mi++) {
                int R = wm1 * 32 + 16 * mi;
                float2 aA = *(const float2*)(sm + OW1 + (R + g) * SX + 8 * k + 2 * t);
                float2 aB = *(const float2*)(sm + OW1 + (R + 8 + g) * SX + 8 * k + 2 * t);
                a[mi][0] = aA.x; a[mi][1] = aB.x; a[mi][2] = aA.y; a[mi][3] = aB.y;
            }
            #pragma unroll
            for (int ni = 0; ni < 2; ni++) {
                int n = wn1 * 16 + 8 * ni + g;
                float b0v = sm[OXS + (8 * k + t) * SX + n];
                float b1v = sm[OXS + (8 * k + t + 4) * SX + n];
                mma8(acc1[0][ni], a[0], b0v, b1v);
                mma8(acc1[1][ni], a[1], b0v, b1v);
            }
        }

        // ---- epilogue: bias+SiLU+gate -> h[ch][px] (STS.64, conflict-free) ----
        #pragma unroll
        for (int mi = 0; mi < 2; mi++) {
            int ch = wm1 * 32 + 16 * mi + g;
            #pragma unroll
            for (int ni = 0; ni < 2; ni++) {
                int px = wn1 * 16 + 8 * ni + 2 * t;
                float v0 = acc1[mi][ni][0] + bia[mi][0];
                float v1 = acc1[mi][ni][1] + bia[mi][0];
                float v2 = acc1[mi][ni][2] + bia[mi][1];
                float v3 = acc1[mi][ni][3] + bia[mi][1];
                float h0 = gate * (v0 / (1.f + __expf(-v0)));
                float h1 = gate * (v1 / (1.f + __expf(-v1)));
                float h2 = gate * (v2 / (1.f + __expf(-v2)));
                float h3 = gate * (v3 / (1.f + __expf(-v3)));
                *(float2*)(sm + OHS + ch * SX + px)       = make_float2(tf32f(h0), tf32f(h1));
                *(float2*)(sm + OHS + (ch + 8) * SX + px) = make_float2(tf32f(h2), tf32f(h3));
            }
        }

        CPA_WAIT0();       // W2(it) landed
        __syncthreads();   // h + W2 visible; W1/x reads quiesced

        // ---- W1(it+1) cp.async (lands during GEMM2) ----
        if (it < 7) {
            const int en = (it + 1 >= 4) ? e1 : e0;
            const int jn = (it + 1) & 3;
            const float* w1s = sW1 + (size_t)(en * 4 + jn) * 64 * SX;
            #pragma unroll
            for (int i = 0; i < 4; i++) {
                int f = tid + i * NT, row = f >> 5, seg = f & 31;
                CPA16(smb + (uint32_t)(OW1 + row * SX + seg * 4) * 4, w1s + row * SX + seg * 4);
            }
            CPA_COMMIT();
        }

        // ---- GEMM2: D2[oc 32][px 32] per warp; A=W2 frag, B=h scalar ----
        #pragma unroll 4
        for (int k = 0; k < 8; k++) {
            float a[2][4];
            #pragma unroll
            for (int mi = 0; mi < 2; mi++) {
                int R = wm2 * 32 + 16 * mi;
                float2 aA = *(const float2*)(sm + OW2 + (R + g) * SW + 8 * k + 2 * t);
                float2 aB = *(const float2*)(sm + OW2 + (R + 8 + g) * SW + 8 * k + 2 * t);
                a[mi][0] = aA.x; a[mi][1] = aB.x; a[mi][2] = aA.y; a[mi][3] = aB.y;
            }
            #pragma unroll
            for (int ni = 0; ni < 4; ni++) {
                int n = wn2 * 32 + 8 * ni + g;
                float b0v = sm[OHS + (8 * k + t) * SX + n];
                float b1v = sm[OHS + (8 * k + t + 4) * SX + n];
                mma8(acc2[0][ni], a[0], b0v, b1v);
                mma8(acc2[1][ni], a[1], b0v, b1v);
            }
        }

        if (it < 7) CPA_WAIT0();
        __syncthreads();
    }

    // ---- final store: acc2 + gated b2 -> out (STG.64 pairs) ----
    {
        float* ob = out + (size_t)b * COUT * HW;
        #pragma unroll
        for (int mi = 0; mi < 2; mi++) {
            int oc0 = wm2 * 32 + 16 * mi + g;
            float gba = sm[OGB + oc0], gbb = sm[OGB + oc0 + 8];
            #pragma unroll
            for (int ni = 0; ni < 4; ni++) {
                int pxg = p0 + wn2 * 32 + 8 * ni + 2 * t;
                if (pxg + 1 < HW) {
                    *(float2*)(ob + (size_t)oc0 * HW + pxg) =
                        make_float2(acc2[mi][ni][0] + gba, acc2[mi][ni][1] + gba);
                    *(float2*)(ob + (size_t)(oc0 + 8) * HW + pxg) =
                        make_float2(acc2[mi][ni][2] + gbb, acc2[mi][ni][3] + gbb);
                }
            }
        }
    }
}

extern "C" void kernel_launch(void* const* d_in, const int* in_sizes, int n_in,
                              void* d_out, int out_size) {
    const float* x   = (const float*)d_in[0];
    const float* wts = (const float*)d_in[1];
    const int*   idx = (const int*)d_in[2];
    const float* W1  = (const float*)d_in[3];
    const float* b1  = (const float*)d_in[4];
    const float* W2  = (const float*)d_in[5];
    const float* b2  = (const float*)d_in[6];
    float* out = (float*)d_out;
    (void)in_sizes; (void)n_in; (void)out_size;

    prep_idx<<<1, 256>>>(idx);
    prep_w<<<512, 512>>>(W1, W2);

    cudaFuncSetAttribute(moe_tf32, cudaFuncAttributeMaxDynamicSharedMemorySize, SMB);
    dim3 grid(NTILE, 128);
    moe_tf32<<<grid, NT, SMB>>>(x, wts, b1, b2, out);
}